// round 1
// baseline (speedup 1.0000x reference)
#include <cuda_runtime.h>
#include <math.h>

#define E   128
#define KC  12
#define BV  4096
#define RD  65536

#define LOG2PI  1.8378770664093453f
#define SQRT2C  1.4142135623730951f
#define SQRTPI  1.7724538509055159f

// ---------------- device globals (no allocation allowed) ----------------
__device__ float g_unit[KC*E];        // normalized artifact directions
__device__ float g_inv_std2[E];       // 1/std_e^2
__device__ float g_sum_log_std;
__device__ float g_lsm[KC];           // log softmax of cluster weights
__device__ float g_kA[KC];            // mu + lambda*sigma^2
__device__ float g_kB[KC];            // 2*mu + lambda*sigma^2
__device__ float g_kInvS[KC];         // 1/(sqrt2*sigma)
__device__ float g_kC[KC];            // log(lambda/2)
__device__ float g_kHL[KC];           // lambda/2
__device__ float g_kOrthC[KC];        // -(E-1)/2*log2pi - (E-1)*log(as)
__device__ float g_kI2A[KC];          // 1/(2*as^2)
__device__ int   g_off[BV+1];         // segment offsets (prefix of alt_counts)
__device__ float g_scratch[RD*(KC+1)];// per-read: [nonart, art_0..art_11]

// ---------------- P0: precompute small stuff ----------------
__global__ void precompute_kernel(const float* __restrict__ dirs,
                                  const float* __restrict__ stde,
                                  const float* __restrict__ mu,
                                  const float* __restrict__ sig,
                                  const float* __restrict__ lam,
                                  const float* __restrict__ asd,
                                  const float* __restrict__ w,
                                  const int*   __restrict__ counts)
{
    __shared__ float red[128];
    __shared__ int   ip[129];
    int t = threadIdx.x;

    // inv std^2 and sum log std
    float sv = stde[t];
    g_inv_std2[t] = 1.f/(sv*sv);
    red[t] = logf(sv);
    __syncthreads();
    for (int s=64; s>0; s>>=1){ if (t<s) red[t]+=red[t+s]; __syncthreads(); }
    if (t==0) g_sum_log_std = red[0];
    __syncthreads();

    // normalize directions
    for (int k=0; k<KC; k++){
        float d = dirs[k*E+t];
        red[t] = d*d;
        __syncthreads();
        for (int s=64; s>0; s>>=1){ if (t<s) red[t]+=red[t+s]; __syncthreads(); }
        float inv = 1.f/sqrtf(red[0]);
        __syncthreads();
        g_unit[k*E+t] = d*inv;
    }

    // per-cluster constants
    if (t < KC){
        float m=mu[t], s_=sig[t], l=lam[t], a=asd[t];
        float A = m + l*s_*s_;
        g_kA[t]    = A;
        g_kB[t]    = m + A;                 // 2mu + lambda*sigma^2
        g_kInvS[t] = 1.f/(SQRT2C*s_);
        g_kC[t]    = logf(0.5f*l);
        g_kHL[t]   = 0.5f*l;
        g_kOrthC[t]= -0.5f*(float)(E-1)*LOG2PI - (float)(E-1)*logf(a);
        g_kI2A[t]  = 1.f/(2.f*a*a);
    }

    // log softmax of cluster weights (K=12, serial on t==0 is fine)
    if (t==0){
        float mx = -1e30f;
        for (int k=0;k<KC;k++) mx = fmaxf(mx, w[k]);
        float s = 0.f;
        for (int k=0;k<KC;k++) s += expf(w[k]-mx);
        float lse = mx + logf(s);
        for (int k=0;k<KC;k++) g_lsm[k] = w[k] - lse;
    }

    // prefix scan of counts (4096 = 128 threads x 32)
    int base = t*32, s0 = 0;
    for (int i=0;i<32;i++) s0 += counts[base+i];
    ip[t+1] = s0;
    __syncthreads();
    if (t==0){ ip[0]=0; for (int i=1;i<=128;i++) ip[i]+=ip[i-1]; }
    __syncthreads();
    int run = ip[t];
    for (int i=0;i<32;i++){ g_off[base+i] = run; run += counts[base+i]; }
    if (t==127) g_off[BV] = run;
}

// ---------------- P1: fused rotate-GEMM + per-read log-liks ----------------
#define AS_LD   132
#define SM_A    0
#define SM_B    16896
#define SM_U    33792
#define SM_IS2  35328
#define SM_PART 35456
#define SM_FLOATS 37248
#define SMEM_BYTES (SM_FLOATS*4)

__device__ __forceinline__ unsigned long long dup2(float x){
    unsigned long long r;
    asm("mov.b64 %0, {%1, %1};" : "=l"(r) : "f"(x));
    return r;
}
#define FFMA2(d,a,b) asm("fma.rn.f32x2 %0, %1, %2, %0;" : "+l"(d) : "l"(a), "l"(b))

__global__ void __launch_bounds__(256,1)
main_kernel(const float* __restrict__ alt,
            const float* __restrict__ trans,
            const float* __restrict__ rot)
{
    extern __shared__ float smem[];
    float* A_s   = smem + SM_A;    // [k][read], ld=132
    float* B_s   = smem + SM_B;    // [k][col],  ld=132  (Rot^T)
    float* u_s   = smem + SM_U;    // [K][E]
    float* is2_s = smem + SM_IS2;  // [E]
    float* part_s= smem + SM_PART; // [128][14]

    const int tid = threadIdx.x;
    const int r0  = blockIdx.x * 128;

    // load Rot transposed:  B_s[k][j] = Rot[j][k]
    for (int idx=tid; idx<E*E; idx+=256){
        int j = idx>>7, k = idx&127;
        B_s[k*AS_LD + j] = rot[idx];
    }
    // load translated alt tile: A_s[e][r] = alt[r][e] + trans[e]
    for (int idx=tid; idx<E*E; idx+=256){
        int rr = idx>>7, e = idx&127;
        A_s[e*AS_LD + rr] = alt[(size_t)(r0+rr)*E + e] + trans[e];
    }
    for (int idx=tid; idx<KC*E; idx+=256) u_s[idx] = g_unit[idx];
    if (tid < E) is2_s[tid] = g_inv_std2[tid];
    __syncthreads();

    // GEMM: x[r][j] = sum_k a[r][k] * B_s[k][j] ; 8 reads x 8 cols per thread,
    // columns packed in pairs for fma.rn.f32x2 (FFMA2).
    const int ty = tid>>4, tx = tid&15;
    unsigned long long acc[8][4];
    #pragma unroll
    for (int i=0;i<8;i++)
        #pragma unroll
        for (int j=0;j<4;j++) acc[i][j] = 0ull;

    const float* Ab = A_s + ty*8;
    const float* Bb = B_s + tx*8;

    #pragma unroll 2
    for (int k=0; k<E; k++){
        float4 a0 = *(const float4*)(Ab + k*AS_LD);
        float4 a1 = *(const float4*)(Ab + k*AS_LD + 4);
        ulonglong2 b0 = *(const ulonglong2*)(Bb + k*AS_LD);
        ulonglong2 b1 = *(const ulonglong2*)(Bb + k*AS_LD + 4);
        unsigned long long av[8];
        av[0]=dup2(a0.x); av[1]=dup2(a0.y); av[2]=dup2(a0.z); av[3]=dup2(a0.w);
        av[4]=dup2(a1.x); av[5]=dup2(a1.y); av[6]=dup2(a1.z); av[7]=dup2(a1.w);
        unsigned long long bv[4] = {b0.x, b0.y, b1.x, b1.y};
        #pragma unroll
        for (int i=0;i<8;i++){
            #pragma unroll
            for (int j=0;j<4;j++) FFMA2(acc[i][j], av[i], bv[j]);
        }
    }
    __syncthreads();   // everyone done reading B_s

    // write x-tile into smem (reuse B region), unpadded ld=128
    float* X_s = B_s;
    #pragma unroll
    for (int i=0;i<8;i++){
        unsigned long long* p = (unsigned long long*)(X_s + (ty*8+i)*E + tx*8);
        p[0]=acc[i][0]; p[1]=acc[i][1]; p[2]=acc[i][2]; p[3]=acc[i][3];
    }
    __syncthreads();

    // per-read epilogue: 2 threads per read, 64 columns each, diagonal order
    const int r = tid & 127;
    const int h = tid >> 7;
    float s2 = 0.f, nx = 0.f;
    float dot[KC];
    #pragma unroll
    for (int k=0;k<KC;k++) dot[k]=0.f;

    const int coff = r + h*64;
    for (int cc=0; cc<64; cc++){
        int c = (coff + cc) & 127;
        float x  = X_s[r*E + c];
        float x2 = x*x;
        nx += x2;
        s2 = fmaf(x2, is2_s[c], s2);
        #pragma unroll
        for (int k=0;k<KC;k++) dot[k] = fmaf(x, u_s[k*E+c], dot[k]);
    }
    if (h==1){
        float* p = part_s + r*14;
        p[0]=s2; p[1]=nx;
        #pragma unroll
        for (int k=0;k<KC;k++) p[2+k]=dot[k];
    }
    __syncthreads();
    if (h==0){
        const float* p = part_s + r*14;
        s2 += p[0]; nx += p[1];
        #pragma unroll
        for (int k=0;k<KC;k++) dot[k] += p[2+k];

        float nonart = -0.5f*(float)E*LOG2PI - g_sum_log_std - 0.5f*s2;
        size_t rg = (size_t)(r0 + r)*(KC+1);
        g_scratch[rg] = nonart;
        #pragma unroll
        for (int k=0;k<KC;k++){
            float dk    = dot[k];
            float orth2 = nx - dk*dk;
            float oll   = g_kOrthC[k] - orth2*g_kI2A[k];
            float z     = (g_kA[k] - dk)*g_kInvS[k];
            float lec;
            if (z > 5.f){
                float z2=z*z, z4=z2*z2, z6=z4*z2;
                lec = -z2 - logf(z*SQRTPI)
                      + log1pf(-1.f/(2.f*z2) + 3.f/(4.f*z4) - 15.f/(8.f*z6));
            } else {
                lec = logf(erfcf(z));
            }
            float par = g_kC[k] + lec + g_kHL[k]*(g_kB[k] - 2.f*dk);
            g_scratch[rg + 1 + k] = oll + par;
        }
    }
}

// ---------------- P2: ragged segment sums + logits ----------------
__global__ void reduce_kernel(float* __restrict__ out)
{
    int b    = blockIdx.x;
    int lane = threadIdx.x;       // 32 threads
    int lo = g_off[b], hi = g_off[b+1];

    float acc = 0.f;
    if (lane < KC+1){
        for (int r=lo; r<hi; r++) acc += g_scratch[(size_t)r*(KC+1) + lane];
        if (lane >= 1) acc += g_lsm[lane-1];
    }
    float nonart = __shfl_sync(0xffffffffu, acc, 0);
    float v = (lane>=1 && lane<KC+1) ? acc : -1e30f;
    float m = v;
    for (int o=16;o>0;o>>=1) m = fmaxf(m, __shfl_xor_sync(0xffffffffu, m, o));
    float e = (lane>=1 && lane<KC+1) ? expf(v-m) : 0.f;
    for (int o=16;o>0;o>>=1) e += __shfl_xor_sync(0xffffffffu, e, o);
    float lse = m + logf(e);
    float logits = lse - nonart;

    if (lane==0)    out[b] = 20.f*tanhf(logits*(1.f/20.f));
    if (lane<KC+1)  out[BV + b*(KC+1) + lane] = acc;
}

// ---------------- launch ----------------
extern "C" void kernel_launch(void* const* d_in, const int* in_sizes, int n_in,
                              void* d_out, int out_size)
{
    const float* alt   = (const float*)d_in[0];
    // d_in[1] = ref_re: transformed but never used by the reference; skipped.
    const float* trans = (const float*)d_in[2];
    const float* rot   = (const float*)d_in[3];
    const float* stde  = (const float*)d_in[4];
    const float* dirs  = (const float*)d_in[5];
    const float* mu    = (const float*)d_in[6];
    const float* sig   = (const float*)d_in[7];
    const float* lam   = (const float*)d_in[8];
    const float* asd   = (const float*)d_in[9];
    const float* w     = (const float*)d_in[10];
    const int*   cnt   = (const int*)d_in[11];
    float* out = (float*)d_out;

    cudaFuncSetAttribute(main_kernel, cudaFuncAttributeMaxDynamicSharedMemorySize,
                         SMEM_BYTES);

    precompute_kernel<<<1, 128>>>(dirs, stde, mu, sig, lam, asd, w, cnt);
    main_kernel<<<RD/128, 256, SMEM_BYTES>>>(alt, trans, rot);
    reduce_kernel<<<BV, 32>>>(out);
}

// round 2
// speedup vs baseline: 1.1305x; 1.1305x over previous
#include <cuda_runtime.h>
#include <math.h>

#define E   128
#define KC  12
#define BV  4096
#define RD  65536

#define LOG2PI  1.8378770664093453f
#define SQRT2C  1.4142135623730951f
#define SQRTPI  1.7724538509055159f

// ---------------- device globals ----------------
__device__ float g_inv_std[E];          // 1/sigma_e
__device__ float g_sum_log_std;
__device__ float g_lsm[KC];
__device__ float g_kA[KC];              // mu + lambda*sigma^2
__device__ float g_kB[KC];              // 2mu + lambda*sigma^2
__device__ float g_kInvS[KC];           // 1/(sqrt2*sigma)
__device__ float g_kC[KC];              // log(lambda/2)
__device__ float g_kHL[KC];             // lambda/2
__device__ float g_kOrthC[KC];
__device__ float g_kI2A[KC];            // 1/(2 as^2)
__device__ float g_P[E*KC];             // Rot^T @ unit_k, row-major [e][k]
__device__ int   g_off[BV+1];
__device__ float g_scratch[(KC+1)*RD];  // TRANSPOSED: [component][read]

// ---------------- K0: constants + prefix scan (1 block, 512 thr) ----------------
__global__ void k0_consts(const float* __restrict__ stde,
                          const float* __restrict__ mu,
                          const float* __restrict__ sig,
                          const float* __restrict__ lam,
                          const float* __restrict__ asd,
                          const float* __restrict__ w,
                          const int*   __restrict__ counts)
{
    __shared__ float red[4];
    __shared__ int   wsum[16];
    const int t = threadIdx.x;
    const unsigned full = 0xffffffffu;

    // 1/sigma and sum(log sigma)
    float lv = 0.f;
    if (t < E){ float s = stde[t]; g_inv_std[t] = 1.f/s; lv = logf(s); }
    for (int o=16;o>0;o>>=1) lv += __shfl_xor_sync(full, lv, o);
    if (t < E && (t&31)==0) red[t>>5] = lv;

    if (t < KC){
        float m=mu[t], s_=sig[t], l=lam[t], a=asd[t];
        float A = m + l*s_*s_;
        g_kA[t]    = A;
        g_kB[t]    = m + A;
        g_kInvS[t] = 1.f/(SQRT2C*s_);
        g_kC[t]    = logf(0.5f*l);
        g_kHL[t]   = 0.5f*l;
        g_kOrthC[t]= -0.5f*(float)(E-1)*LOG2PI - (float)(E-1)*logf(a);
        g_kI2A[t]  = 1.f/(2.f*a*a);
    }
    if (t==480){ // any single thread not busy above
        float mx = -1e30f;
        for (int k=0;k<KC;k++) mx = fmaxf(mx, w[k]);
        float s = 0.f;
        for (int k=0;k<KC;k++) s += expf(w[k]-mx);
        float lse = mx + logf(s);
        for (int k=0;k<KC;k++) g_lsm[k] = w[k] - lse;
    }
    __syncthreads();
    if (t==0) g_sum_log_std = red[0]+red[1]+red[2]+red[3];

    // prefix scan of counts: 512 threads x 8
    const int base = t*8;
    int c[8]; int s0 = 0;
    #pragma unroll
    for (int i=0;i<8;i++){ c[i] = counts[base+i]; s0 += c[i]; }
    int incl = s0;
    for (int o=1;o<32;o<<=1){
        int v = __shfl_up_sync(full, incl, o);
        if ((t&31) >= o) incl += v;
    }
    if ((t&31)==31) wsum[t>>5] = incl;
    __syncthreads();
    if (t==0){ int run=0; for (int i=0;i<16;i++){ int v=wsum[i]; wsum[i]=run; run+=v; } }
    __syncthreads();
    int run = wsum[t>>5] + incl - s0;
    #pragma unroll
    for (int i=0;i<8;i++){ g_off[base+i] = run; run += c[i]; }
    if (t==511) g_off[BV] = run;
}

// ---------------- K1: P = Rot^T @ unit (128 blocks x 128 thr) ----------------
__global__ void k1_proj(const float* __restrict__ rot,
                        const float* __restrict__ dirs)
{
    __shared__ float rcol[E];
    const int e = blockIdx.x, t = threadIdx.x;
    const unsigned full = 0xffffffffu;
    rcol[t] = rot[t*E + e];     // column e of Rot
    __syncthreads();
    const int w = t>>5, l = t&31;
    #pragma unroll
    for (int kk=0; kk<3; kk++){
        int k = w*3 + kk;
        float ds = 0.f, ns = 0.f;
        #pragma unroll
        for (int j=l; j<E; j+=32){
            float d = dirs[k*E + j];
            ds = fmaf(rcol[j], d, ds);
            ns = fmaf(d, d, ns);
        }
        for (int o=16;o>0;o>>=1){
            ds += __shfl_xor_sync(full, ds, o);
            ns += __shfl_xor_sync(full, ns, o);
        }
        if (l==0) g_P[e*KC + k] = ds * rsqrtf(ns);
    }
}

// ---------------- K2: fused GEMM + per-read log-liks ----------------
#define AS_LD   132
#define SM_A    0
#define SM_B    16896
#define SM_P    33792
#define SM_S2   35328
#define SM_D1   37504
#define SM_DF   39168
#define SM_KON  40832
#define SM_FLOATS 40920
#define SMEM_BYTES (SM_FLOATS*4)

__device__ __forceinline__ unsigned long long dup2(float x){
    unsigned long long r;
    asm("mov.b64 %0, {%1, %1};" : "=l"(r) : "f"(x));
    return r;
}
#define FFMA2(d,a,b) asm("fma.rn.f32x2 %0, %1, %2, %0;" : "+l"(d) : "l"(a), "l"(b))
__device__ __forceinline__ void unpack2(unsigned long long v, float& lo, float& hi){
    asm("mov.b64 {%0, %1}, %2;" : "=f"(lo), "=f"(hi) : "l"(v));
}

__global__ void __launch_bounds__(256,1)
main_kernel(const float* __restrict__ alt,
            const float* __restrict__ trans,
            const float* __restrict__ rot)
{
    extern __shared__ float smem[];
    float* A_s  = smem + SM_A;    // [e][r], ld=132 (translated alt)
    float* B_s  = smem + SM_B;    // [e][j], ld=132 (Rot^T scaled by 1/sigma_j)
    float* P_s  = smem + SM_P;    // [e][12]
    float* S2_s = smem + SM_S2;   // [128][17] s2 partials per tx
    float* D1_s = smem + SM_D1;   // [128][13] h1 partials (12 dots + nx)
    float* DF_s = smem + SM_DF;   // [128][13] full dots + nx
    float* KON  = smem + SM_KON;  // 7*12 cluster consts

    const int tid = threadIdx.x;
    const int r0  = blockIdx.x * 128;

    // B_s[k][j] = Rot[j][k] / sigma_j
    for (int idx=tid; idx<E*E; idx+=256){
        int j = idx>>7, k = idx&127;
        B_s[k*AS_LD + j] = rot[idx] * g_inv_std[j];
    }
    // A_s[e][r] = alt[r0+r][e] + trans[e]
    for (int idx=tid; idx<E*E; idx+=256){
        int rr = idx>>7, e = idx&127;
        A_s[e*AS_LD + rr] = alt[(size_t)(r0+rr)*E + e] + trans[e];
    }
    for (int idx=tid; idx<E*KC; idx+=256) P_s[idx] = g_P[idx];
    if (tid < KC){
        KON[tid]      = g_kA[tid];
        KON[12+tid]   = g_kB[tid];
        KON[24+tid]   = g_kInvS[tid];
        KON[36+tid]   = g_kC[tid];
        KON[48+tid]   = g_kHL[tid];
        KON[60+tid]   = g_kOrthC[tid];
        KON[72+tid]   = g_kI2A[tid];
    }
    __syncthreads();

    // GEMM: y[r][j] = sum_e a'[r][e] * B_s[e][j]; 8 reads x 8 cols (4 col-pairs) per thread
    const int ty = tid>>4, tx = tid&15;
    unsigned long long acc[8][4];
    #pragma unroll
    for (int i=0;i<8;i++)
        #pragma unroll
        for (int j=0;j<4;j++) acc[i][j] = 0ull;

    const float* Ab = A_s + ty*8;
    const float* Bb = B_s + tx*8;

    #pragma unroll 2
    for (int k=0; k<E; k++){
        float4 a0 = *(const float4*)(Ab + k*AS_LD);
        float4 a1 = *(const float4*)(Ab + k*AS_LD + 4);
        ulonglong2 b0 = *(const ulonglong2*)(Bb + k*AS_LD);
        ulonglong2 b1 = *(const ulonglong2*)(Bb + k*AS_LD + 4);
        unsigned long long av[8];
        av[0]=dup2(a0.x); av[1]=dup2(a0.y); av[2]=dup2(a0.z); av[3]=dup2(a0.w);
        av[4]=dup2(a1.x); av[5]=dup2(a1.y); av[6]=dup2(a1.z); av[7]=dup2(a1.w);
        unsigned long long bv[4] = {b0.x, b0.y, b1.x, b1.y};
        #pragma unroll
        for (int i=0;i<8;i++){
            #pragma unroll
            for (int j=0;j<4;j++) FFMA2(acc[i][j], av[i], bv[j]);
        }
    }

    // fold s2 partials directly from accumulators (y = x/sigma componentwise)
    #pragma unroll
    for (int i=0;i<8;i++){
        float s = 0.f;
        #pragma unroll
        for (int j=0;j<4;j++){
            float lo, hi; unpack2(acc[i][j], lo, hi);
            s = fmaf(lo, lo, s);
            s = fmaf(hi, hi, s);
        }
        S2_s[(ty*8+i)*17 + tx] = s;
    }
    __syncthreads();

    // dot/nx pass over A tile: 2 threads per read, 64 features each
    const int r = tid & 127;
    const int h = tid >> 7;
    float nx = 0.f;
    float dot[KC];
    #pragma unroll
    for (int k=0;k<KC;k++) dot[k]=0.f;

    for (int cc=0; cc<64; cc++){
        int e = h*64 + cc;
        float a = A_s[e*AS_LD + r];
        nx = fmaf(a, a, nx);
        const float4* pr = (const float4*)(P_s + e*KC);
        float4 p0 = pr[0], p1 = pr[1], p2 = pr[2];
        dot[0]=fmaf(a,p0.x,dot[0]); dot[1]=fmaf(a,p0.y,dot[1]);
        dot[2]=fmaf(a,p0.z,dot[2]); dot[3]=fmaf(a,p0.w,dot[3]);
        dot[4]=fmaf(a,p1.x,dot[4]); dot[5]=fmaf(a,p1.y,dot[5]);
        dot[6]=fmaf(a,p1.z,dot[6]); dot[7]=fmaf(a,p1.w,dot[7]);
        dot[8]=fmaf(a,p2.x,dot[8]); dot[9]=fmaf(a,p2.y,dot[9]);
        dot[10]=fmaf(a,p2.z,dot[10]); dot[11]=fmaf(a,p2.w,dot[11]);
    }
    if (h==1){
        float* q = D1_s + r*13;
        #pragma unroll
        for (int k=0;k<KC;k++) q[k] = dot[k];
        q[12] = nx;
    }
    __syncthreads();
    if (h==0){
        const float* q = D1_s + r*13;
        #pragma unroll
        for (int k=0;k<KC;k++) dot[k] += q[k];
        nx += q[12];
        float s2 = 0.f;
        #pragma unroll
        for (int t=0;t<16;t++) s2 += S2_s[r*17 + t];
        float nonart = -64.f*LOG2PI - g_sum_log_std - 0.5f*s2;
        g_scratch[r0 + r] = nonart;           // component 0, coalesced
        float* f = DF_s + r*13;
        #pragma unroll
        for (int k=0;k<KC;k++) f[k] = dot[k];
        f[12] = nx;
    }
    __syncthreads();

    // EMG + orth log-lik: each thread does 6 clusters for its read
    {
        const float* f = DF_s + r*13;
        float nx2 = f[12];
        const int kb = h*6;
        #pragma unroll
        for (int kk=0; kk<6; kk++){
            int k = kb + kk;
            float dk    = f[k];
            float orth2 = nx2 - dk*dk;
            float oll   = KON[60+k] - orth2*KON[72+k];
            float z     = (KON[k] - dk)*KON[24+k];
            float lec;
            if (z > 5.f){
                float z2=z*z, z4=z2*z2, z6=z4*z2;
                lec = -z2 - logf(z*SQRTPI)
                      + log1pf(-1.f/(2.f*z2) + 3.f/(4.f*z4) - 15.f/(8.f*z6));
            } else {
                lec = logf(erfcf(z));
            }
            float par = KON[36+k] + lec + KON[48+k]*(KON[12+k] - 2.f*dk);
            g_scratch[(size_t)(1+k)*RD + r0 + r] = oll + par;   // coalesced
        }
    }
}

// ---------------- K3: ragged segment sums + logits (warp per variant) ----------------
__global__ void reduce_kernel(float* __restrict__ out)
{
    const int b    = blockIdx.x*4 + (threadIdx.x>>5);
    const int lane = threadIdx.x & 31;
    const unsigned full = 0xffffffffu;
    const int lo = g_off[b], hi = g_off[b+1];

    float acc = 0.f;
    if (lane < KC+1){
        const float* p = g_scratch + (size_t)lane*RD;
        for (int r=lo; r<hi; r++) acc += p[r];
        if (lane >= 1) acc += g_lsm[lane-1];
    }
    float nonart = __shfl_sync(full, acc, 0);
    float v = (lane>=1 && lane<KC+1) ? acc : -1e30f;
    float m = v;
    for (int o=16;o>0;o>>=1) m = fmaxf(m, __shfl_xor_sync(full, m, o));
    float e = (lane>=1 && lane<KC+1) ? expf(v-m) : 0.f;
    for (int o=16;o>0;o>>=1) e += __shfl_xor_sync(full, e, o);
    float lse = m + logf(e);
    float logits = lse - nonart;

    if (lane==0)     out[b] = 20.f*tanhf(logits*(1.f/20.f));
    if (lane<KC+1)   out[BV + b*(KC+1) + lane] = acc;
}

// ---------------- launch ----------------
extern "C" void kernel_launch(void* const* d_in, const int* in_sizes, int n_in,
                              void* d_out, int out_size)
{
    const float* alt   = (const float*)d_in[0];
    // d_in[1] = ref_re: unused by the reference output
    const float* trans = (const float*)d_in[2];
    const float* rot   = (const float*)d_in[3];
    const float* stde  = (const float*)d_in[4];
    const float* dirs  = (const float*)d_in[5];
    const float* mu    = (const float*)d_in[6];
    const float* sig   = (const float*)d_in[7];
    const float* lam   = (const float*)d_in[8];
    const float* asd   = (const float*)d_in[9];
    const float* w     = (const float*)d_in[10];
    const int*   cnt   = (const int*)d_in[11];
    float* out = (float*)d_out;

    cudaFuncSetAttribute(main_kernel, cudaFuncAttributeMaxDynamicSharedMemorySize,
                         SMEM_BYTES);

    k0_consts<<<1, 512>>>(stde, mu, sig, lam, asd, w, cnt);
    k1_proj<<<E, 128>>>(rot, dirs);
    main_kernel<<<RD/128, 256, SMEM_BYTES>>>(alt, trans, rot);
    reduce_kernel<<<BV/4, 128>>>(out);
}